// round 2
// baseline (speedup 1.0000x reference)
#include <cuda_runtime.h>
#include <math.h>

// Problem constants
#define B_    4
#define N_    4096
#define E_    1024
#define H_    16
#define D_    64
#define PD_   64
#define FD_   128          // 2*PD
#define MTOT  16384        // B*N
#define EPSN  1e-4f
#define SCALE 2.0f         // H^0.25 = 16^0.25
#define FSCALE 0.125f      // PD^-0.5

// Scratch (device globals: allocation-free rule).
// g_k doubles as the attention-output buffer (k is dead after kv is formed).
__device__ float g_q [16777216];     // (B,N,E) q proj
__device__ float g_k [16777216];     // (B,N,E) k proj, later ao
__device__ float g_v [16777216];     // (B,N,E) v proj
__device__ float g_kvp[512 * 8192];  // per (bh,chunk) partial kv (128x64)
__device__ float g_kv [64 * 8192];   // per bh kv (128x64)

__device__ __forceinline__ float* sel_buf(int s) {
    return s == 0 ? g_q : (s == 1 ? g_k : g_v);
}

// ---------------------------------------------------------------------------
// SGEMM (NT): Y[M,Nn] = X[M,K] @ W[Nn,K]^T + bias[Nn]
// 128x128 block tile, 32 K-tile, 8x8 per-thread tile, 256 threads.
// xsel/ysel >= 0 select an internal scratch buffer; -1 uses the ext pointer.
// ---------------------------------------------------------------------------
__global__ __launch_bounds__(256) void sgemm_nt_bias(
    const float* __restrict__ Xext, int xsel,
    const float* __restrict__ W, const float* __restrict__ bias,
    float* __restrict__ Yext, int ysel,
    int M, int Nn, int K)
{
    const float* X = (xsel < 0) ? Xext : sel_buf(xsel);
    float*       Y = (ysel < 0) ? Yext : sel_buf(ysel);

    __shared__ float Xs[32][132];
    __shared__ float Ws[32][132];
    const int tid = threadIdx.x;
    const int bm = blockIdx.y * 128;
    const int bn = blockIdx.x * 128;
    const int ty = tid >> 4, tx = tid & 15;

    float acc[8][8];
#pragma unroll
    for (int i = 0; i < 8; i++)
#pragma unroll
        for (int j = 0; j < 8; j++) acc[i][j] = 0.f;

    const float* Xp = X + (size_t)bm * K;
    const float* Wp = W + (size_t)bn * K;

    for (int k0 = 0; k0 < K; k0 += 32) {
#pragma unroll
        for (int l = 0; l < 4; l++) {
            int idx = l * 256 + tid;
            int row = idx >> 3;
            int c8  = idx & 7;
            float4 xv = *(const float4*)(Xp + (size_t)row * K + k0 + c8 * 4);
            Xs[c8*4+0][row] = xv.x; Xs[c8*4+1][row] = xv.y;
            Xs[c8*4+2][row] = xv.z; Xs[c8*4+3][row] = xv.w;
            float4 wv = *(const float4*)(Wp + (size_t)row * K + k0 + c8 * 4);
            Ws[c8*4+0][row] = wv.x; Ws[c8*4+1][row] = wv.y;
            Ws[c8*4+2][row] = wv.z; Ws[c8*4+3][row] = wv.w;
        }
        __syncthreads();
#pragma unroll
        for (int kk = 0; kk < 32; kk++) {
            float a[8], bb[8];
            *(float4*)&a[0]  = *(const float4*)&Xs[kk][ty*8];
            *(float4*)&a[4]  = *(const float4*)&Xs[kk][ty*8+4];
            *(float4*)&bb[0] = *(const float4*)&Ws[kk][tx*8];
            *(float4*)&bb[4] = *(const float4*)&Ws[kk][tx*8+4];
#pragma unroll
            for (int i = 0; i < 8; i++)
#pragma unroll
                for (int j = 0; j < 8; j++)
                    acc[i][j] = fmaf(a[i], bb[j], acc[i][j]);
        }
        __syncthreads();
    }

    float bv[8];
    *(float4*)&bv[0] = *(const float4*)(bias + bn + tx*8);
    *(float4*)&bv[4] = *(const float4*)(bias + bn + tx*8 + 4);
#pragma unroll
    for (int i = 0; i < 8; i++) {
        float* yp = Y + (size_t)(bm + ty*8 + i) * Nn + bn + tx*8;
        float4 o0 = make_float4(acc[i][0]+bv[0], acc[i][1]+bv[1],
                                acc[i][2]+bv[2], acc[i][3]+bv[3]);
        float4 o1 = make_float4(acc[i][4]+bv[4], acc[i][5]+bv[5],
                                acc[i][6]+bv[6], acc[i][7]+bv[7]);
        *(float4*)yp     = o0;
        *(float4*)(yp+4) = o1;
    }
}

// ---------------------------------------------------------------------------
// feat_kv: per (b,h,chunk of 512 rows): normalize k, project (P), sin/cos
// features, accumulate partial kv[128][64] into registers, write to g_kvp.
// grid: 512 = 64 bh * 8 chunks; 256 threads (8 warps, warp-per-row staging).
// ---------------------------------------------------------------------------
__global__ __launch_bounds__(256) void feat_kv_kernel(const float* __restrict__ Pm)
{
    const float* Kb = g_k;
    const float* Vb = g_v;
    __shared__ float Ps[64][68];
    __shared__ float ks[8][68];
    __shared__ float vs[8][64];
    __shared__ float kf[8][128];
    const int tid = threadIdx.x;
    const int lane = tid & 31, warp = tid >> 5;
    const int bid = blockIdx.x;
    const int bh = bid >> 3, ch = bid & 7;
    const int b = bh >> 4, h = bh & 15;

    for (int i = tid; i < 64 * 64; i += 256) Ps[i >> 6][i & 63] = Pm[i];
    __syncthreads();

    const int eg = tid >> 4, dg = tid & 15;   // thread owns e in [eg*8,+8), d in [dg*4,+4)
    float acc[8][4];
#pragma unroll
    for (int i = 0; i < 8; i++)
#pragma unroll
        for (int j = 0; j < 4; j++) acc[i][j] = 0.f;

    const int row0 = ch * 512;
    const size_t hb = (size_t)(b * N_) * E_ + h * 64;

    for (int r0 = 0; r0 < 512; r0 += 8) {
        int row = row0 + r0 + warp;
        const float* kr = Kb + hb + (size_t)row * E_;
        const float* vr = Vb + hb + (size_t)row * E_;
        float k0v = kr[lane], k1v = kr[lane + 32];
        vs[warp][lane]      = vr[lane];
        vs[warp][lane + 32] = vr[lane + 32];
        float ss = k0v * k0v + k1v * k1v;
#pragma unroll
        for (int off = 16; off; off >>= 1) ss += __shfl_xor_sync(0xffffffffu, ss, off);
        float inv = 1.0f / (sqrtf(ss) + EPSN);
        ks[warp][lane]      = k0v * inv;
        ks[warp][lane + 32] = k1v * inv;
        __syncwarp();
        float p0 = 0.f, p1 = 0.f;
#pragma unroll
        for (int d4 = 0; d4 < 16; d4++) {
            float4 kk = *(const float4*)&ks[warp][d4 * 4];
            float4 pa = *(const float4*)&Ps[lane][d4 * 4];
            float4 pb = *(const float4*)&Ps[lane + 32][d4 * 4];
            p0 += kk.x*pa.x + kk.y*pa.y + kk.z*pa.z + kk.w*pa.w;
            p1 += kk.x*pb.x + kk.y*pb.y + kk.z*pb.z + kk.w*pb.w;
        }
        p0 *= SCALE; p1 *= SCALE;
        float s0, c0, s1, c1;
        __sincosf(p0, &s0, &c0);
        __sincosf(p1, &s1, &c1);
        kf[warp][lane]       = s0 * FSCALE;
        kf[warp][lane + 32]  = s1 * FSCALE;
        kf[warp][64 + lane]  = c0 * FSCALE;
        kf[warp][96 + lane]  = c1 * FSCALE;
        __syncthreads();
#pragma unroll
        for (int r = 0; r < 8; r++) {
            float4 v4 = *(const float4*)&vs[r][dg * 4];
            float4 f0 = *(const float4*)&kf[r][eg * 8];
            float4 f1 = *(const float4*)&kf[r][eg * 8 + 4];
            float fa[8] = {f0.x, f0.y, f0.z, f0.w, f1.x, f1.y, f1.z, f1.w};
#pragma unroll
            for (int i = 0; i < 8; i++) {
                acc[i][0] = fmaf(fa[i], v4.x, acc[i][0]);
                acc[i][1] = fmaf(fa[i], v4.y, acc[i][1]);
                acc[i][2] = fmaf(fa[i], v4.z, acc[i][2]);
                acc[i][3] = fmaf(fa[i], v4.w, acc[i][3]);
            }
        }
        __syncthreads();
    }

    float* outp = g_kvp + (size_t)bid * 8192;
#pragma unroll
    for (int i = 0; i < 8; i++)
        *(float4*)(outp + (eg * 8 + i) * 64 + dg * 4) =
            make_float4(acc[i][0], acc[i][1], acc[i][2], acc[i][3]);
}

// ---------------------------------------------------------------------------
// kv reduce over chunks: g_kv[bh] = sum_ch g_kvp[bh*8+ch]
// ---------------------------------------------------------------------------
__global__ __launch_bounds__(256) void kv_reduce_kernel()
{
    int bh = blockIdx.x, tid = threadIdx.x;
    const float4* src = (const float4*)(g_kvp + (size_t)bh * 8 * 8192);
    float4* dst = (float4*)(g_kv + (size_t)bh * 8192);
    for (int i = tid; i < 2048; i += 256) {
        float4 s = src[i];
#pragma unroll
        for (int c = 1; c < 8; c++) {
            float4 t = src[c * 2048 + i];
            s.x += t.x; s.y += t.y; s.z += t.z; s.w += t.w;
        }
        dst[i] = s;
    }
}

// ---------------------------------------------------------------------------
// o_feat: per (b,h,128-row chunk): q features (staged 32 rows at a time),
// then o = qf @ kv. Writes into g_k (reused as ao buffer).
// grid: 64 bh * 32 chunks = 2048 blocks; dyn smem ~67KB.
// ---------------------------------------------------------------------------
__global__ __launch_bounds__(256) void o_feat_kernel(const float* __restrict__ Pm)
{
    const float* Qb = g_q;
    float*       AO = g_k;
    extern __shared__ float sm[];
    float (*Ps)[68]   = (float(*)[68])sm;                         // 64*68 = 4352
    float* kvs        = sm + 4352;                                // 8192 (e-major [128][64])
    float (*qfs)[128] = (float(*)[128])(sm + 4352 + 8192);        // 32*128 = 4096
    float (*qs)[68]   = (float(*)[68])(sm + 4352 + 8192 + 4096);  // 8*68 = 544

    const int tid = threadIdx.x, lane = tid & 31, warp = tid >> 5;
    const int bid = blockIdx.x;
    const int bh = bid >> 5, cb = bid & 31;
    const int b = bh >> 4, h = bh & 15;

    for (int i = tid; i < 4096; i += 256) Ps[i >> 6][i & 63] = Pm[i];
    {
        const float4* kvg = (const float4*)(g_kv + (size_t)bh * 8192);
        float4* kvd = (float4*)kvs;
        for (int i = tid; i < 2048; i += 256) kvd[i] = kvg[i];
    }
    __syncthreads();

    const int rowg = tid >> 5, dg = tid & 31;
    const size_t hb = (size_t)(b * N_) * E_ + h * 64;

    for (int it = 0; it < 128; it += 32) {
        // stage 32 rows of qf (each warp stages 4 rows)
#pragma unroll
        for (int j = 0; j < 4; j++) {
            int rl = warp * 4 + j;
            int row = cb * 128 + it + rl;
            const float* qr = Qb + hb + (size_t)row * E_;
            float q0 = qr[lane], q1 = qr[lane + 32];
            float ss = q0 * q0 + q1 * q1;
#pragma unroll
            for (int off = 16; off; off >>= 1) ss += __shfl_xor_sync(0xffffffffu, ss, off);
            float inv = 1.0f / (sqrtf(ss) + EPSN);
            qs[warp][lane]      = q0 * inv;
            qs[warp][lane + 32] = q1 * inv;
            __syncwarp();
            float p0 = 0.f, p1 = 0.f;
#pragma unroll
            for (int d4 = 0; d4 < 16; d4++) {
                float4 kk = *(const float4*)&qs[warp][d4 * 4];
                float4 pa = *(const float4*)&Ps[lane][d4 * 4];
                float4 pb = *(const float4*)&Ps[lane + 32][d4 * 4];
                p0 += kk.x*pa.x + kk.y*pa.y + kk.z*pa.z + kk.w*pa.w;
                p1 += kk.x*pb.x + kk.y*pb.y + kk.z*pb.z + kk.w*pb.w;
            }
            p0 *= SCALE; p1 *= SCALE;
            float s0, c0, s1, c1;
            __sincosf(p0, &s0, &c0);
            __sincosf(p1, &s1, &c1);
            qfs[rl][lane]      = s0 * FSCALE;
            qfs[rl][lane + 32] = s1 * FSCALE;
            qfs[rl][64 + lane] = c0 * FSCALE;
            qfs[rl][96 + lane] = c1 * FSCALE;
            __syncwarp();
        }
        __syncthreads();

        // o = qf @ kv  (thread: 4 rows x 2 d-cols, e inner)
        float acc[4][2] = {{0,0},{0,0},{0,0},{0,0}};
#pragma unroll
        for (int e4 = 0; e4 < 32; e4++) {
            float qa[4][4];
#pragma unroll
            for (int i = 0; i < 4; i++) {
                float4 t = *(const float4*)&qfs[rowg * 4 + i][e4 * 4];
                qa[i][0] = t.x; qa[i][1] = t.y; qa[i][2] = t.z; qa[i][3] = t.w;
            }
#pragma unroll
            for (int ee = 0; ee < 4; ee++) {
                float2 kv2 = *(const float2*)&kvs[(e4 * 4 + ee) * 64 + dg * 2];
#pragma unroll
                for (int i = 0; i < 4; i++) {
                    acc[i][0] = fmaf(qa[i][ee], kv2.x, acc[i][0]);
                    acc[i][1] = fmaf(qa[i][ee], kv2.y, acc[i][1]);
                }
            }
        }
#pragma unroll
        for (int i = 0; i < 4; i++) {
            int row = cb * 128 + it + rowg * 4 + i;
            float* ao = AO + hb + (size_t)row * E_ + dg * 2;
            *(float2*)ao = make_float2(acc[i][0], acc[i][1]);
        }
        __syncthreads();
    }
}

// ---------------------------------------------------------------------------
extern "C" void kernel_launch(void* const* d_in, const int* in_sizes, int n_in,
                              void* d_out, int out_size)
{
    const float* x  = (const float*)d_in[0];
    const float* Wq = (const float*)d_in[1];
    const float* bq = (const float*)d_in[2];
    const float* Wk = (const float*)d_in[3];
    const float* bk = (const float*)d_in[4];
    const float* Wv = (const float*)d_in[5];
    const float* bv = (const float*)d_in[6];
    const float* Wo = (const float*)d_in[7];
    const float* bo = (const float*)d_in[8];
    const float* P  = (const float*)d_in[9];
    float* out = (float*)d_out;

    cudaFuncSetAttribute(o_feat_kernel,
                         cudaFuncAttributeMaxDynamicSharedMemorySize, 68736);

    dim3 gg(E_ / 128, MTOT / 128);
    // q/k/v projections into internal buffers (ysel 0/1/2)
    sgemm_nt_bias<<<gg, 256>>>(x, -1, Wq, bq, nullptr, 0, MTOT, E_, E_);
    sgemm_nt_bias<<<gg, 256>>>(x, -1, Wk, bk, nullptr, 1, MTOT, E_, E_);
    sgemm_nt_bias<<<gg, 256>>>(x, -1, Wv, bv, nullptr, 2, MTOT, E_, E_);
    feat_kv_kernel<<<512, 256>>>(P);
    kv_reduce_kernel<<<64, 256>>>();
    o_feat_kernel<<<2048, 256, 68736>>>(P);   // writes ao into g_k
    // output projection: X = g_k (xsel=1), Y = external out
    sgemm_nt_bias<<<gg, 256>>>(nullptr, 1, Wo, bo, out, -1, MTOT, E_, E_);
}

// round 4
// speedup vs baseline: 1.8641x; 1.8641x over previous
#include <cuda_runtime.h>
#include <cuda_bf16.h>
#include <math.h>
#include <cstdint>

// Problem constants
#define B_    4
#define N_    4096
#define E_    1024
#define H_    16
#define MTOT  16384        // B*N
#define EPSN  1e-4f
#define SCALE 2.0f         // H^0.25
#define FSCALE 0.125f      // PD^-0.5

// ---------------------------------------------------------------------------
// Scratch (device globals: allocation-free rule)
// ---------------------------------------------------------------------------
__device__ float g_q [16777216];     // (B,N,E) q proj fp32
__device__ float g_k [16777216];     // (B,N,E) k proj fp32
__device__ float g_v [16777216];     // (B,N,E) v proj fp32
__device__ float g_kvp[4194304];     // per (bh,chunk) partial kv (128x64)
__device__ float g_kv [524288];      // per bh kv (128x64)
__device__ __nv_bfloat16 g_xhi [16777216];
__device__ __nv_bfloat16 g_xlo [16777216];
__device__ __nv_bfloat16 g_aohi[16777216];
__device__ __nv_bfloat16 g_aolo[16777216];
__device__ __nv_bfloat16 g_whi [4194304];   // 4 x 1024x1024
__device__ __nv_bfloat16 g_wlo [4194304];

__device__ __forceinline__ float* sel_buf(int s) {
    return s == 0 ? g_q : (s == 1 ? g_k : g_v);
}

// ---------------------------------------------------------------------------
// PTX helpers (base-target sm_103 safe: mma.sync / ldmatrix / cp.async only)
// ---------------------------------------------------------------------------
__device__ __forceinline__ uint32_t smem_u32(const void* p) {
    uint32_t a;
    asm("{ .reg .u64 t; cvta.to.shared.u64 t, %1; cvt.u32.u64 %0, t; }"
        : "=r"(a) : "l"(p));
    return a;
}
__device__ __forceinline__ void cpasync16(uint32_t dst, const void* src) {
    asm volatile("cp.async.cg.shared.global [%0], [%1], 16;" :: "r"(dst), "l"(src));
}
#define CP_COMMIT()  asm volatile("cp.async.commit_group;" ::: "memory")
#define CP_WAIT(n)   asm volatile("cp.async.wait_group %0;" :: "n"(n) : "memory")

__device__ __forceinline__ void ldsm4(uint32_t* r, uint32_t addr) {
    asm volatile("ldmatrix.sync.aligned.m8n8.x4.shared.b16 {%0,%1,%2,%3}, [%4];"
                 : "=r"(r[0]), "=r"(r[1]), "=r"(r[2]), "=r"(r[3]) : "r"(addr));
}
__device__ __forceinline__ void mma16816(float* d, const uint32_t* a, const uint32_t* b) {
    asm volatile(
        "mma.sync.aligned.m16n8k16.row.col.f32.bf16.bf16.f32 "
        "{%0,%1,%2,%3}, {%4,%5,%6,%7}, {%8,%9}, {%0,%1,%2,%3};"
        : "+f"(d[0]), "+f"(d[1]), "+f"(d[2]), "+f"(d[3])
        : "r"(a[0]), "r"(a[1]), "r"(a[2]), "r"(a[3]), "r"(b[0]), "r"(b[1]));
}

// ---------------------------------------------------------------------------
// Split conversion: fp32 -> bf16 hi + bf16 lo.  dsel: 0=x, 1..4=W0..W3
// ---------------------------------------------------------------------------
__global__ __launch_bounds__(256) void conv_split(const float* __restrict__ src,
                                                  int dsel, int n4)
{
    __nv_bfloat16 *hi, *lo;
    if (dsel == 0) { hi = g_xhi; lo = g_xlo; }
    else { hi = g_whi + (size_t)(dsel - 1) * 1048576; lo = g_wlo + (size_t)(dsel - 1) * 1048576; }
    int i = blockIdx.x * 256 + threadIdx.x;
    if (i >= n4) return;
    float4 v = ((const float4*)src)[i];
    __nv_bfloat16 h0 = __float2bfloat16(v.x);
    __nv_bfloat16 h1 = __float2bfloat16(v.y);
    __nv_bfloat16 h2 = __float2bfloat16(v.z);
    __nv_bfloat16 h3 = __float2bfloat16(v.w);
    __nv_bfloat162* hp = (__nv_bfloat162*)hi;
    __nv_bfloat162* lp = (__nv_bfloat162*)lo;
    hp[i * 2]     = __nv_bfloat162(h0, h1);
    hp[i * 2 + 1] = __nv_bfloat162(h2, h3);
    lp[i * 2]     = __nv_bfloat162(__float2bfloat16(v.x - __bfloat162float(h0)),
                                   __float2bfloat16(v.y - __bfloat162float(h1)));
    lp[i * 2 + 1] = __nv_bfloat162(__float2bfloat16(v.z - __bfloat162float(h2)),
                                   __float2bfloat16(v.w - __bfloat162float(h3)));
}

// ---------------------------------------------------------------------------
// Tensor-core GEMM (NT) via mma.sync bf16 split:
// Y[16384,1024] = X @ W^T + bias, with X/W given as bf16 hi/lo pairs.
// 128x128 block, K-chunk 32, 256 thr (2x4 warps, 64x32 warp tile),
// cp.async double-buffered smem: 4 tiles (Ahi|Alo|Bhi|Blo), 80B padded rows.
// ---------------------------------------------------------------------------
#define TILE_B  10240      // 128 rows * 80 bytes
#define STAGE_B 40960      // 4 tiles
__global__ __launch_bounds__(256, 1) void gemm_mma(
    int xsel, int wsel, const float* __restrict__ bias,
    float* __restrict__ Yext, int ysel)
{
    const __nv_bfloat16* Xhi = xsel ? g_aohi : g_xhi;
    const __nv_bfloat16* Xlo = xsel ? g_aolo : g_xlo;
    const __nv_bfloat16* Whi = g_whi + (size_t)wsel * 1048576;
    const __nv_bfloat16* Wlo = g_wlo + (size_t)wsel * 1048576;
    float* Y = (ysel < 0) ? Yext : sel_buf(ysel);

    extern __shared__ char smem[];
    const uint32_t sbase = smem_u32(smem);
    const int tid = threadIdx.x;
    const int lane = tid & 31, wid = tid >> 5;
    const int wm = wid & 1, wn = wid >> 1;
    const int m0 = blockIdx.y * 128, n0 = blockIdx.x * 128;

    float acc[4][4][4];
#pragma unroll
    for (int a = 0; a < 4; a++)
#pragma unroll
        for (int b = 0; b < 4; b++)
#pragma unroll
            for (int c = 0; c < 4; c++) acc[a][b][c] = 0.f;

    // chunk loader: 2048 x 16B segments, 8 per thread
    auto issue_chunk = [&](int c) {
        const int k0 = c * 32;
        const uint32_t dstb = sbase + (uint32_t)(c & 1) * STAGE_B;
#pragma unroll
        for (int it = 0; it < 8; it++) {
            const int id  = it * 256 + tid;
            const int tile = id >> 9;           // constant per it
            const int rem = id & 511;
            const int row = rem >> 2, seg = rem & 3;
            const __nv_bfloat16* src;
            if (tile == 0)      src = Xhi + (size_t)(m0 + row) * 1024 + k0 + seg * 8;
            else if (tile == 1) src = Xlo + (size_t)(m0 + row) * 1024 + k0 + seg * 8;
            else if (tile == 2) src = Whi + (size_t)(n0 + row) * 1024 + k0 + seg * 8;
            else                src = Wlo + (size_t)(n0 + row) * 1024 + k0 + seg * 8;
            cpasync16(dstb + tile * TILE_B + row * 80 + seg * 16, src);
        }
        CP_COMMIT();
    };

    issue_chunk(0);
    for (int c = 0; c < 32; c++) {
        if (c + 1 < 32) { issue_chunk(c + 1); CP_WAIT(1); }
        else            { CP_WAIT(0); }
        __syncthreads();
        const uint32_t st = sbase + (uint32_t)(c & 1) * STAGE_B;
#pragma unroll
        for (int ks = 0; ks < 2; ks++) {
            uint32_t ahi[4][4], alo[4][4];
            const uint32_t arow = (uint32_t)(lane & 15);
            const uint32_t acol = (uint32_t)(ks * 16 + (lane >> 4) * 8);
#pragma unroll
            for (int mt = 0; mt < 4; mt++) {
                const uint32_t off = (uint32_t)(wm * 64 + mt * 16 + arow) * 80 + acol * 2;
                ldsm4(ahi[mt], st + off);
                ldsm4(alo[mt], st + TILE_B + off);
            }
            uint32_t bhi[2][4], blo[2][4];
            const uint32_t brow = (uint32_t)(((lane >> 4) << 3) + (lane & 7));
            const uint32_t bcol = (uint32_t)(ks * 16 + ((lane >> 3) & 1) * 8);
#pragma unroll
            for (int nb = 0; nb < 2; nb++) {
                const uint32_t off = (uint32_t)(wn * 32 + nb * 16 + brow) * 80 + bcol * 2;
                ldsm4(bhi[nb], st + 2 * TILE_B + off);
                ldsm4(blo[nb], st + 3 * TILE_B + off);
            }
#pragma unroll
            for (int mt = 0; mt < 4; mt++)
#pragma unroll
                for (int nt = 0; nt < 4; nt++) {
                    const uint32_t* bh = &bhi[nt >> 1][(nt & 1) * 2];
                    const uint32_t* bl = &blo[nt >> 1][(nt & 1) * 2];
                    mma16816(acc[mt][nt], ahi[mt], bh);
                    mma16816(acc[mt][nt], ahi[mt], bl);
                    mma16816(acc[mt][nt], alo[mt], bh);
                }
        }
        __syncthreads();
    }

    // Epilogue
    const int mrow = lane >> 2, ncol = (lane & 3) * 2;
#pragma unroll
    for (int mt = 0; mt < 4; mt++)
#pragma unroll
        for (int nt = 0; nt < 4; nt++) {
            const int m = m0 + wm * 64 + mt * 16 + mrow;
            const int n = n0 + wn * 32 + nt * 8 + ncol;
            const float b0 = __ldg(&bias[n]), b1 = __ldg(&bias[n + 1]);
            float* y0 = Y + (size_t)m * 1024 + n;
            float* y1 = Y + (size_t)(m + 8) * 1024 + n;
            *(float2*)y0 = make_float2(acc[mt][nt][0] + b0, acc[mt][nt][1] + b1);
            *(float2*)y1 = make_float2(acc[mt][nt][2] + b0, acc[mt][nt][3] + b1);
        }
}

// ---------------------------------------------------------------------------
// feat_kv: per (b,h,chunk of 512 rows): normalize k, project (P), sin/cos
// features, accumulate partial kv[128][64] into registers -> g_kvp.
// ---------------------------------------------------------------------------
__global__ __launch_bounds__(256) void feat_kv_kernel(const float* __restrict__ Pm)
{
    const float* Kb = g_k;
    const float* Vb = g_v;
    __shared__ float Ps[64][68];
    __shared__ float ks[8][68];
    __shared__ float vs[8][64];
    __shared__ float kf[8][128];
    const int tid = threadIdx.x;
    const int lane = tid & 31, warp = tid >> 5;
    const int bid = blockIdx.x;
    const int bh = bid >> 3, ch = bid & 7;
    const int b = bh >> 4, h = bh & 15;

    for (int i = tid; i < 64 * 64; i += 256) Ps[i >> 6][i & 63] = Pm[i];
    __syncthreads();

    const int eg = tid >> 4, dg = tid & 15;
    float acc[8][4];
#pragma unroll
    for (int i = 0; i < 8; i++)
#pragma unroll
        for (int j = 0; j < 4; j++) acc[i][j] = 0.f;

    const int row0 = ch * 512;
    const size_t hb = (size_t)(b * N_) * E_ + h * 64;

    for (int r0 = 0; r0 < 512; r0 += 8) {
        int row = row0 + r0 + warp;
        const float* kr = Kb + hb + (size_t)row * E_;
        const float* vr = Vb + hb + (size_t)row * E_;
        float k0v = kr[lane], k1v = kr[lane + 32];
        vs[warp][lane]      = vr[lane];
        vs[warp][lane + 32] = vr[lane + 32];
        float ss = k0v * k0v + k1v * k1v;
#pragma unroll
        for (int off = 16; off; off >>= 1) ss += __shfl_xor_sync(0xffffffffu, ss, off);
        float inv = 1.0f / (sqrtf(ss) + EPSN);
        ks[warp][lane]      = k0v * inv;
        ks[warp][lane + 32] = k1v * inv;
        __syncwarp();
        float p0 = 0.f, p1 = 0.f;
#pragma unroll
        for (int d4 = 0; d4 < 16; d4++) {
            float4 kk = *(const float4*)&ks[warp][d4 * 4];
            float4 pa = *(const float4*)&Ps[lane][d4 * 4];
            float4 pb = *(const float4*)&Ps[lane + 32][d4 * 4];
            p0 += kk.x*pa.x + kk.y*pa.y + kk.z*pa.z + kk.w*pa.w;
            p1 += kk.x*pb.x + kk.y*pb.y + kk.z*pb.z + kk.w*pb.w;
        }
        p0 *= SCALE; p1 *= SCALE;
        float s0, c0, s1, c1;
        __sincosf(p0, &s0, &c0);
        __sincosf(p1, &s1, &c1);
        kf[warp][lane]       = s0 * FSCALE;
        kf[warp][lane + 32]  = s1 * FSCALE;
        kf[warp][64 + lane]  = c0 * FSCALE;
        kf[warp][96 + lane]  = c1 * FSCALE;
        __syncthreads();
#pragma unroll
        for (int r = 0; r < 8; r++) {
            float4 v4 = *(const float4*)&vs[r][dg * 4];
            float4 f0 = *(const float4*)&kf[r][eg * 8];
            float4 f1 = *(const float4*)&kf[r][eg * 8 + 4];
            float fa[8] = {f0.x, f0.y, f0.z, f0.w, f1.x, f1.y, f1.z, f1.w};
#pragma unroll
            for (int i = 0; i < 8; i++) {
                acc[i][0] = fmaf(fa[i], v4.x, acc[i][0]);
                acc[i][1] = fmaf(fa[i], v4.y, acc[i][1]);
                acc[i][2] = fmaf(fa[i], v4.z, acc[i][2]);
                acc[i][3] = fmaf(fa[i], v4.w, acc[i][3]);
            }
        }
        __syncthreads();
    }

    float* outp = g_kvp + (size_t)bid * 8192;
#pragma unroll
    for (int i = 0; i < 8; i++)
        *(float4*)(outp + (eg * 8 + i) * 64 + dg * 4) =
            make_float4(acc[i][0], acc[i][1], acc[i][2], acc[i][3]);
}

// ---------------------------------------------------------------------------
__global__ __launch_bounds__(256) void kv_reduce_kernel()
{
    int bh = blockIdx.x, tid = threadIdx.x;
    const float4* src = (const float4*)(g_kvp + (size_t)bh * 8 * 8192);
    float4* dst = (float4*)(g_kv + (size_t)bh * 8192);
    for (int i = tid; i < 2048; i += 256) {
        float4 s = src[i];
#pragma unroll
        for (int c = 1; c < 8; c++) {
            float4 t = src[c * 2048 + i];
            s.x += t.x; s.y += t.y; s.z += t.z; s.w += t.w;
        }
        dst[i] = s;
    }
}

// ---------------------------------------------------------------------------
// o_feat: per (b,h,128-row chunk): q features then o = qf @ kv.
// Writes ao directly as bf16 hi/lo splits (input to final tensor GEMM).
// ---------------------------------------------------------------------------
__global__ __launch_bounds__(256) void o_feat_kernel(const float* __restrict__ Pm)
{
    const float* Qb = g_q;
    extern __shared__ float sm[];
    float (*Ps)[68]   = (float(*)[68])sm;                         // 64*68
    float* kvs        = sm + 4352;                                // 8192
    float (*qfs)[128] = (float(*)[128])(sm + 4352 + 8192);        // 32*128
    float (*qs)[68]   = (float(*)[68])(sm + 4352 + 8192 + 4096);  // 8*68

    const int tid = threadIdx.x, lane = tid & 31, warp = tid >> 5;
    const int bid = blockIdx.x;
    const int bh = bid >> 5, cb = bid & 31;
    const int b = bh >> 4, h = bh & 15;

    for (int i = tid; i < 4096; i += 256) Ps[i >> 6][i & 63] = Pm[i];
    {
        const float4* kvg = (const float4*)(g_kv + (size_t)bh * 8192);
        float4* kvd = (float4*)kvs;
        for (int i = tid; i < 2048; i += 256) kvd[i] = kvg[i];
    }
    __syncthreads();

    const int rowg = tid >> 5, dg = tid & 31;
    const size_t hb = (size_t)(b * N_) * E_ + h * 64;

    for (int it = 0; it < 128; it += 32) {
#pragma unroll
        for (int j = 0; j < 4; j++) {
            int rl = warp * 4 + j;
            int row = cb * 128 + it + rl;
            const float* qr = Qb + hb + (size_t)row * E_;
            float q0 = qr[lane], q1 = qr[lane + 32];
            float ss = q0 * q0 + q1 * q1;
#pragma unroll
            for (int off = 16; off; off >>= 1) ss += __shfl_xor_sync(0xffffffffu, ss, off);
            float inv = 1.0f / (sqrtf(ss) + EPSN);
            qs[warp][lane]      = q0 * inv;
            qs[warp][lane + 32] = q1 * inv;
            __syncwarp();
            float p0 = 0.f, p1 = 0.f;
#pragma unroll
            for (int d4 = 0; d4 < 16; d4++) {
                float4 kk = *(const float4*)&qs[warp][d4 * 4];
                float4 pa = *(const float4*)&Ps[lane][d4 * 4];
                float4 pb = *(const float4*)&Ps[lane + 32][d4 * 4];
                p0 += kk.x*pa.x + kk.y*pa.y + kk.z*pa.z + kk.w*pa.w;
                p1 += kk.x*pb.x + kk.y*pb.y + kk.z*pb.z + kk.w*pb.w;
            }
            p0 *= SCALE; p1 *= SCALE;
            float s0, c0, s1, c1;
            __sincosf(p0, &s0, &c0);
            __sincosf(p1, &s1, &c1);
            qfs[rl][lane]      = s0 * FSCALE;
            qfs[rl][lane + 32] = s1 * FSCALE;
            qfs[rl][64 + lane] = c0 * FSCALE;
            qfs[rl][96 + lane] = c1 * FSCALE;
            __syncwarp();
        }
        __syncthreads();

        float acc[4][2] = {{0,0},{0,0},{0,0},{0,0}};
#pragma unroll
        for (int e4 = 0; e4 < 32; e4++) {
            float qa[4][4];
#pragma unroll
            for (int i = 0; i < 4; i++) {
                float4 t = *(const float4*)&qfs[rowg * 4 + i][e4 * 4];
                qa[i][0] = t.x; qa[i][1] = t.y; qa[i][2] = t.z; qa[i][3] = t.w;
            }
#pragma unroll
            for (int ee = 0; ee < 4; ee++) {
                float2 kv2 = *(const float2*)&kvs[(e4 * 4 + ee) * 64 + dg * 2];
#pragma unroll
                for (int i = 0; i < 4; i++) {
                    acc[i][0] = fmaf(qa[i][ee], kv2.x, acc[i][0]);
                    acc[i][1] = fmaf(qa[i][ee], kv2.y, acc[i][1]);
                }
            }
        }
#pragma unroll
        for (int i = 0; i < 4; i++) {
            int row = cb * 128 + it + rowg * 4 + i;
            size_t idx = hb + (size_t)row * E_ + dg * 2;
            float a0 = acc[i][0], a1 = acc[i][1];
            __nv_bfloat16 h0 = __float2bfloat16(a0);
            __nv_bfloat16 h1 = __float2bfloat16(a1);
            *(__nv_bfloat162*)&g_aohi[idx] = __nv_bfloat162(h0, h1);
            *(__nv_bfloat162*)&g_aolo[idx] = __nv_bfloat162(
                __float2bfloat16(a0 - __bfloat162float(h0)),
                __float2bfloat16(a1 - __bfloat162float(h1)));
        }
        __syncthreads();
    }
}

// ---------------------------------------------------------------------------
extern "C" void kernel_launch(void* const* d_in, const int* in_sizes, int n_in,
                              void* d_out, int out_size)
{
    const float* x  = (const float*)d_in[0];
    const float* Wq = (const float*)d_in[1];
    const float* bq = (const float*)d_in[2];
    const float* Wk = (const float*)d_in[3];
    const float* bk = (const float*)d_in[4];
    const float* Wv = (const float*)d_in[5];
    const float* bv = (const float*)d_in[6];
    const float* Wo = (const float*)d_in[7];
    const float* bo = (const float*)d_in[8];
    const float* P  = (const float*)d_in[9];
    float* out = (float*)d_out;

    cudaFuncSetAttribute(o_feat_kernel,
                         cudaFuncAttributeMaxDynamicSharedMemorySize, 68736);
    cudaFuncSetAttribute(gemm_mma,
                         cudaFuncAttributeMaxDynamicSharedMemorySize, 2 * STAGE_B);

    // Split conversions
    conv_split<<<16384, 256>>>(x,  0, 4194304);
    conv_split<<<1024,  256>>>(Wq, 1, 262144);
    conv_split<<<1024,  256>>>(Wk, 2, 262144);
    conv_split<<<1024,  256>>>(Wv, 3, 262144);
    conv_split<<<1024,  256>>>(Wo, 4, 262144);

    dim3 gg(8, 128);   // (N/128, M/128)
    gemm_mma<<<gg, 256, 2 * STAGE_B>>>(0, 0, bq, nullptr, 0);   // q
    gemm_mma<<<gg, 256, 2 * STAGE_B>>>(0, 1, bk, nullptr, 1);   // k
    gemm_mma<<<gg, 256, 2 * STAGE_B>>>(0, 2, bv, nullptr, 2);   // v

    feat_kv_kernel<<<512, 256>>>(P);
    kv_reduce_kernel<<<64, 256>>>();
    o_feat_kernel<<<2048, 256, 68736>>>(P);       // -> g_aohi/g_aolo

    gemm_mma<<<gg, 256, 2 * STAGE_B>>>(1, 3, bo, out, -1);      // out proj
}

// round 6
// speedup vs baseline: 2.1067x; 1.1301x over previous
#include <cuda_runtime.h>
#include <cuda_bf16.h>
#include <math.h>
#include <cstdint>

// Problem constants
#define B_    4
#define N_    4096
#define E_    1024
#define H_    16
#define MTOT  16384        // B*N
#define EPSN  1e-4f
#define SCALE 2.0f         // H^0.25
#define FSCALE 0.125f      // PD^-0.5

// ---------------------------------------------------------------------------
// Scratch (device globals: allocation-free rule)
// ---------------------------------------------------------------------------
__device__ float g_q [16777216];     // (B,N,E) q proj fp32
__device__ float g_k [16777216];     // (B,N,E) k proj fp32
__device__ float g_v [16777216];     // (B,N,E) v proj fp32
__device__ float g_kvp[8388608];     // per (bh,chunk) partial kv (128x64), 1024 blocks
__device__ float g_kv [524288];      // per bh kv (128x64)
__device__ __nv_bfloat16 g_xhi [16777216];
__device__ __nv_bfloat16 g_xlo [16777216];
__device__ __nv_bfloat16 g_aohi[16777216];
__device__ __nv_bfloat16 g_aolo[16777216];
__device__ __nv_bfloat16 g_whi [4194304];   // 4 x 1024x1024
__device__ __nv_bfloat16 g_wlo [4194304];

__device__ __forceinline__ float* sel_buf(int s) {
    return s == 0 ? g_q : (s == 1 ? g_k : g_v);
}

// ---------------------------------------------------------------------------
// PTX helpers (base-target sm_103 safe: mma.sync / ldmatrix / cp.async only)
// ---------------------------------------------------------------------------
__device__ __forceinline__ uint32_t smem_u32(const void* p) {
    uint32_t a;
    asm("{ .reg .u64 t; cvta.to.shared.u64 t, %1; cvt.u32.u64 %0, t; }"
        : "=r"(a) : "l"(p));
    return a;
}
__device__ __forceinline__ void cpasync16(uint32_t dst, const void* src) {
    asm volatile("cp.async.cg.shared.global [%0], [%1], 16;" :: "r"(dst), "l"(src));
}
#define CP_COMMIT()  asm volatile("cp.async.commit_group;" ::: "memory")
#define CP_WAIT(n)   asm volatile("cp.async.wait_group %0;" :: "n"(n) : "memory")

__device__ __forceinline__ void ldsm4(uint32_t* r, uint32_t addr) {
    asm volatile("ldmatrix.sync.aligned.m8n8.x4.shared.b16 {%0,%1,%2,%3}, [%4];"
                 : "=r"(r[0]), "=r"(r[1]), "=r"(r[2]), "=r"(r[3]) : "r"(addr));
}
__device__ __forceinline__ void mma16816(float* d, const uint32_t* a, const uint32_t* b) {
    asm volatile(
        "mma.sync.aligned.m16n8k16.row.col.f32.bf16.bf16.f32 "
        "{%0,%1,%2,%3}, {%4,%5,%6,%7}, {%8,%9}, {%0,%1,%2,%3};"
        : "+f"(d[0]), "+f"(d[1]), "+f"(d[2]), "+f"(d[3])
        : "r"(a[0]), "r"(a[1]), "r"(a[2]), "r"(a[3]), "r"(b[0]), "r"(b[1]));
}

// ---------------------------------------------------------------------------
// Split conversion: fp32 -> bf16 hi + bf16 lo.  dsel: 0=x, 1..4=W0..W3
// ---------------------------------------------------------------------------
__global__ __launch_bounds__(256) void conv_split(const float* __restrict__ src,
                                                  int dsel, int n4)
{
    __nv_bfloat16 *hi, *lo;
    if (dsel == 0) { hi = g_xhi; lo = g_xlo; }
    else { hi = g_whi + (size_t)(dsel - 1) * 1048576; lo = g_wlo + (size_t)(dsel - 1) * 1048576; }
    int i = blockIdx.x * 256 + threadIdx.x;
    if (i >= n4) return;
    float4 v = ((const float4*)src)[i];
    __nv_bfloat16 h0 = __float2bfloat16(v.x);
    __nv_bfloat16 h1 = __float2bfloat16(v.y);
    __nv_bfloat16 h2 = __float2bfloat16(v.z);
    __nv_bfloat16 h3 = __float2bfloat16(v.w);
    __nv_bfloat162* hp = (__nv_bfloat162*)hi;
    __nv_bfloat162* lp = (__nv_bfloat162*)lo;
    hp[i * 2]     = __nv_bfloat162(h0, h1);
    hp[i * 2 + 1] = __nv_bfloat162(h2, h3);
    lp[i * 2]     = __nv_bfloat162(__float2bfloat16(v.x - __bfloat162float(h0)),
                                   __float2bfloat16(v.y - __bfloat162float(h1)));
    lp[i * 2 + 1] = __nv_bfloat162(__float2bfloat16(v.z - __bfloat162float(h2)),
                                   __float2bfloat16(v.w - __bfloat162float(h3)));
}

// ---------------------------------------------------------------------------
// Tensor-core GEMM (NT) via mma.sync bf16 split:
// Y[16384,1024] = X @ W^T + bias, with X/W given as bf16 hi/lo pairs.
// 128x128 block, K-chunk 32, 256 thr (2x4 warps, 64x32 warp tile),
// cp.async 3-stage smem pipeline: 4 tiles (Ahi|Alo|Bhi|Blo), 80B padded rows,
// single __syncthreads per chunk.
// ---------------------------------------------------------------------------
#define TILE_B  10240      // 128 rows * 80 bytes
#define STAGE_B 40960      // 4 tiles
#define NSTAGE  3
__global__ __launch_bounds__(256, 1) void gemm_mma(
    int xsel, int wsel, const float* __restrict__ bias,
    float* __restrict__ Yext, int ysel)
{
    const __nv_bfloat16* Xhi = xsel ? g_aohi : g_xhi;
    const __nv_bfloat16* Xlo = xsel ? g_aolo : g_xlo;
    const __nv_bfloat16* Whi = g_whi + (size_t)wsel * 1048576;
    const __nv_bfloat16* Wlo = g_wlo + (size_t)wsel * 1048576;
    float* Y = (ysel < 0) ? Yext : sel_buf(ysel);

    extern __shared__ char smem[];
    const uint32_t sbase = smem_u32(smem);
    const int tid = threadIdx.x;
    const int lane = tid & 31, wid = tid >> 5;
    const int wm = wid & 1, wn = wid >> 1;
    const int m0 = blockIdx.y * 128, n0 = blockIdx.x * 128;

    float acc[4][4][4];
#pragma unroll
    for (int a = 0; a < 4; a++)
#pragma unroll
        for (int b = 0; b < 4; b++)
#pragma unroll
            for (int c = 0; c < 4; c++) acc[a][b][c] = 0.f;

    // chunk loader: 2048 x 16B segments, 8 per thread (always commits a group)
    auto issue_chunk = [&](int c) {
        if (c < 32) {
            const int k0 = c * 32;
            const uint32_t dstb = sbase + (uint32_t)(c % NSTAGE) * STAGE_B;
#pragma unroll
            for (int it = 0; it < 8; it++) {
                const int id  = it * 256 + tid;
                const int tile = id >> 9;           // constant per it
                const int rem = id & 511;
                const int row = rem >> 2, seg = rem & 3;
                const __nv_bfloat16* src;
                if (tile == 0)      src = Xhi + (size_t)(m0 + row) * 1024 + k0 + seg * 8;
                else if (tile == 1) src = Xlo + (size_t)(m0 + row) * 1024 + k0 + seg * 8;
                else if (tile == 2) src = Whi + (size_t)(n0 + row) * 1024 + k0 + seg * 8;
                else                src = Wlo + (size_t)(n0 + row) * 1024 + k0 + seg * 8;
                cpasync16(dstb + tile * TILE_B + row * 80 + seg * 16, src);
            }
        }
        CP_COMMIT();
    };

    issue_chunk(0);
    issue_chunk(1);
    for (int c = 0; c < 32; c++) {
        CP_WAIT(1);            // chunk c complete (groups retire in order)
        __syncthreads();       // visibility across threads; frees buf (c-1)%3
        const uint32_t st = sbase + (uint32_t)(c % NSTAGE) * STAGE_B;
#pragma unroll
        for (int ks = 0; ks < 2; ks++) {
            uint32_t ahi[4][4], alo[4][4];
            const uint32_t arow = (uint32_t)(lane & 15);
            const uint32_t acol = (uint32_t)(ks * 16 + (lane >> 4) * 8);
#pragma unroll
            for (int mt = 0; mt < 4; mt++) {
                const uint32_t off = (uint32_t)(wm * 64 + mt * 16 + arow) * 80 + acol * 2;
                ldsm4(ahi[mt], st + off);
                ldsm4(alo[mt], st + TILE_B + off);
            }
            uint32_t bhi[2][4], blo[2][4];
            const uint32_t brow = (uint32_t)(((lane >> 4) << 3) + (lane & 7));
            const uint32_t bcol = (uint32_t)(ks * 16 + ((lane >> 3) & 1) * 8);
#pragma unroll
            for (int nb = 0; nb < 2; nb++) {
                const uint32_t off = (uint32_t)(wn * 32 + nb * 16 + brow) * 80 + bcol * 2;
                ldsm4(bhi[nb], st + 2 * TILE_B + off);
                ldsm4(blo[nb], st + 3 * TILE_B + off);
            }
#pragma unroll
            for (int mt = 0; mt < 4; mt++)
#pragma unroll
                for (int nt = 0; nt < 4; nt++) {
                    const uint32_t* bh = &bhi[nt >> 1][(nt & 1) * 2];
                    const uint32_t* bl = &blo[nt >> 1][(nt & 1) * 2];
                    mma16816(acc[mt][nt], ahi[mt], bh);
                    mma16816(acc[mt][nt], ahi[mt], bl);
                    mma16816(acc[mt][nt], alo[mt], bh);
                }
        }
        issue_chunk(c + 2);    // writes buf (c+2)%3 == (c-1)%3 (freed above)
    }

    // Epilogue
    const int mrow = lane >> 2, ncol = (lane & 3) * 2;
#pragma unroll
    for (int mt = 0; mt < 4; mt++)
#pragma unroll
        for (int nt = 0; nt < 4; nt++) {
            const int m = m0 + wm * 64 + mt * 16 + mrow;
            const int n = n0 + wn * 32 + nt * 8 + ncol;
            const float b0 = __ldg(&bias[n]), b1 = __ldg(&bias[n + 1]);
            float* y0 = Y + (size_t)m * 1024 + n;
            float* y1 = Y + (size_t)(m + 8) * 1024 + n;
            *(float2*)y0 = make_float2(acc[mt][nt][0] + b0, acc[mt][nt][1] + b1);
            *(float2*)y1 = make_float2(acc[mt][nt][2] + b0, acc[mt][nt][3] + b1);
        }
}

// ---------------------------------------------------------------------------
// feat_kv: per (b,h,chunk of 256 rows): normalize k, project (P), sin/cos
// features, accumulate partial kv[128][64] into registers -> g_kvp.
// grid: 1024 = 64 bh * 16 chunks; 256 threads.
// ---------------------------------------------------------------------------
__global__ __launch_bounds__(256) void feat_kv_kernel(const float* __restrict__ Pm)
{
    const float* Kb = g_k;
    const float* Vb = g_v;
    __shared__ float Ps[64][68];
    __shared__ float ks[8][68];
    __shared__ float vs[8][64];
    __shared__ float kf[8][128];
    const int tid = threadIdx.x;
    const int lane = tid & 31, warp = tid >> 5;
    const int bid = blockIdx.x;
    const int bh = bid >> 4, ch = bid & 15;
    const int b = bh >> 4, h = bh & 15;

    for (int i = tid; i < 64 * 64; i += 256) Ps[i >> 6][i & 63] = Pm[i];
    __syncthreads();

    const int eg = tid >> 4, dg = tid & 15;
    float acc[8][4];
#pragma unroll
    for (int i = 0; i < 8; i++)
#pragma unroll
        for (int j = 0; j < 4; j++) acc[i][j] = 0.f;

    const int row0 = ch * 256;
    const size_t hb = (size_t)(b * N_) * E_ + h * 64;

    for (int r0 = 0; r0 < 256; r0 += 8) {
        int row = row0 + r0 + warp;
        const float* kr = Kb + hb + (size_t)row * E_;
        const float* vr = Vb + hb + (size_t)row * E_;
        float k0v = kr[lane], k1v = kr[lane + 32];
        vs[warp][lane]      = vr[lane];
        vs[warp][lane + 32] = vr[lane + 32];
        float ss = k0v * k0v + k1v * k1v;
#pragma unroll
        for (int off = 16; off; off >>= 1) ss += __shfl_xor_sync(0xffffffffu, ss, off);
        float inv = 1.0f / (sqrtf(ss) + EPSN);
        ks[warp][lane]      = k0v * inv;
        ks[warp][lane + 32] = k1v * inv;
        __syncwarp();
        float p0 = 0.f, p1 = 0.f;
#pragma unroll
        for (int d4 = 0; d4 < 16; d4++) {
            float4 kk = *(const float4*)&ks[warp][d4 * 4];
            float4 pa = *(const float4*)&Ps[lane][d4 * 4];
            float4 pb = *(const float4*)&Ps[lane + 32][d4 * 4];
            p0 += kk.x*pa.x + kk.y*pa.y + kk.z*pa.z + kk.w*pa.w;
            p1 += kk.x*pb.x + kk.y*pb.y + kk.z*pb.z + kk.w*pb.w;
        }
        p0 *= SCALE; p1 *= SCALE;
        float s0, c0, s1, c1;
        __sincosf(p0, &s0, &c0);
        __sincosf(p1, &s1, &c1);
        kf[warp][lane]       = s0 * FSCALE;
        kf[warp][lane + 32]  = s1 * FSCALE;
        kf[warp][64 + lane]  = c0 * FSCALE;
        kf[warp][96 + lane]  = c1 * FSCALE;
        __syncthreads();
#pragma unroll
        for (int r = 0; r < 8; r++) {
            float4 v4 = *(const float4*)&vs[r][dg * 4];
            float4 f0 = *(const float4*)&kf[r][eg * 8];
            float4 f1 = *(const float4*)&kf[r][eg * 8 + 4];
            float fa[8] = {f0.x, f0.y, f0.z, f0.w, f1.x, f1.y, f1.z, f1.w};
#pragma unroll
            for (int i = 0; i < 8; i++) {
                acc[i][0] = fmaf(fa[i], v4.x, acc[i][0]);
                acc[i][1] = fmaf(fa[i], v4.y, acc[i][1]);
                acc[i][2] = fmaf(fa[i], v4.z, acc[i][2]);
                acc[i][3] = fmaf(fa[i], v4.w, acc[i][3]);
            }
        }
        __syncthreads();
    }

    float* outp = g_kvp + (size_t)bid * 8192;
#pragma unroll
    for (int i = 0; i < 8; i++)
        *(float4*)(outp + (eg * 8 + i) * 64 + dg * 4) =
            make_float4(acc[i][0], acc[i][1], acc[i][2], acc[i][3]);
}

// ---------------------------------------------------------------------------
// kv reduce over 16 chunks: g_kv[bh] = sum_ch g_kvp[bh*16+ch]
// ---------------------------------------------------------------------------
__global__ __launch_bounds__(256) void kv_reduce_kernel()
{
    int bh = blockIdx.x, tid = threadIdx.x;
    const float4* src = (const float4*)(g_kvp + (size_t)bh * 16 * 8192);
    float4* dst = (float4*)(g_kv + (size_t)bh * 8192);
    for (int i = tid; i < 2048; i += 256) {
        float4 s = src[i];
#pragma unroll
        for (int c = 1; c < 16; c++) {
            float4 t = src[c * 2048 + i];
            s.x += t.x; s.y += t.y; s.z += t.z; s.w += t.w;
        }
        dst[i] = s;
    }
}

// ---------------------------------------------------------------------------
// o_feat: per (b,h,128-row chunk): q features then o = qf @ kv.
// Writes ao directly as bf16 hi/lo splits (input to final tensor GEMM).
// ---------------------------------------------------------------------------
__global__ __launch_bounds__(256) void o_feat_kernel(const float* __restrict__ Pm)
{
    const float* Qb = g_q;
    extern __shared__ float sm[];
    float (*Ps)[68]   = (float(*)[68])sm;                         // 64*68
    float* kvs        = sm + 4352;                                // 8192
    float (*qfs)[128] = (float(*)[128])(sm + 4352 + 8192);        // 32*128
    float (*qs)[68]   = (float(*)[68])(sm + 4352 + 8192 + 4096);  // 8*68

    const int tid = threadIdx.x, lane = tid & 31, warp = tid >> 5;
    const int bid = blockIdx.x;
    const int bh = bid >> 5, cb = bid & 31;
    const int b = bh >> 4, h = bh & 15;

    for (int i = tid; i < 4096; i += 256) Ps[i >> 6][i & 63] = Pm[i];
    {
        const float4* kvg = (const float4*)(g_kv + (size_t)bh * 8192);
        float4* kvd = (float4*)kvs;
        for (int i = tid; i < 2048; i += 256) kvd[i] = kvg[i];
    }
    __syncthreads();

    const int rowg = tid >> 5, dg = tid & 31;
    const size_t hb = (size_t)(b * N_) * E_ + h * 64;

    for (int it = 0; it < 128; it += 32) {
#pragma unroll
        for (int j = 0; j < 4; j++) {
            int rl = warp * 4 + j;
            int row = cb * 128 + it + rl;
            const float* qr = Qb + hb + (size_t)row * E_;
            float q0 = qr[lane], q1 = qr[lane + 32];
            float ss = q0 * q0 + q1 * q1;
#pragma unroll
            for (int off = 16; off; off >>= 1) ss += __shfl_xor_sync(0xffffffffu, ss, off);
            float inv = 1.0f / (sqrtf(ss) + EPSN);
            qs[warp][lane]      = q0 * inv;
            qs[warp][lane + 32] = q1 * inv;
            __syncwarp();
            float p0 = 0.f, p1 = 0.f;
#pragma unroll
            for (int d4 = 0; d4 < 16; d4++) {
                float4 kk = *(const float4*)&qs[warp][d4 * 4];
                float4 pa = *(const float4*)&Ps[lane][d4 * 4];
                float4 pb = *(const float4*)&Ps[lane + 32][d4 * 4];
                p0 += kk.x*pa.x + kk.y*pa.y + kk.z*pa.z + kk.w*pa.w;
                p1 += kk.x*pb.x + kk.y*pb.y + kk.z*pb.z + kk.w*pb.w;
            }
            p0 *= SCALE; p1 *= SCALE;
            float s0, c0, s1, c1;
            __sincosf(p0, &s0, &c0);
            __sincosf(p1, &s1, &c1);
            qfs[rl][lane]      = s0 * FSCALE;
            qfs[rl][lane + 32] = s1 * FSCALE;
            qfs[rl][64 + lane] = c0 * FSCALE;
            qfs[rl][96 + lane] = c1 * FSCALE;
            __syncwarp();
        }
        __syncthreads();

        float acc[4][2] = {{0,0},{0,0},{0,0},{0,0}};
#pragma unroll
        for (int e4 = 0; e4 < 32; e4++) {
            float qa[4][4];
#pragma unroll
            for (int i = 0; i < 4; i++) {
                float4 t = *(const float4*)&qfs[rowg * 4 + i][e4 * 4];
                qa[i][0] = t.x; qa[i][1] = t.y; qa[i][2] = t.z; qa[i][3] = t.w;
            }
#pragma unroll
            for (int ee = 0; ee < 4; ee++) {
                float2 kv2 = *(const float2*)&kvs[(e4 * 4 + ee) * 64 + dg * 2];
#pragma unroll
                for (int i = 0; i < 4; i++) {
                    acc[i][0] = fmaf(qa[i][ee], kv2.x, acc[i][0]);
                    acc[i][1] = fmaf(qa[i][ee], kv2.y, acc[i][1]);
                }
            }
        }
#pragma unroll
        for (int i = 0; i < 4; i++) {
            int row = cb * 128 + it + rowg * 4 + i;
            size_t idx = hb + (size_t)row * E_ + dg * 2;
            float a0 = acc[i][0], a1 = acc[i][1];
            __nv_bfloat16 h0 = __float2bfloat16(a0);
            __nv_bfloat16 h1 = __float2bfloat16(a1);
            *(__nv_bfloat162*)&g_aohi[idx] = __nv_bfloat162(h0, h1);
            *(__nv_bfloat162*)&g_aolo[idx] = __nv_bfloat162(
                __float2bfloat16(a0 - __bfloat162float(h0)),
                __float2bfloat16(a1 - __bfloat162float(h1)));
        }
        __syncthreads();
    }
}

// ---------------------------------------------------------------------------
extern "C" void kernel_launch(void* const* d_in, const int* in_sizes, int n_in,
                              void* d_out, int out_size)
{
    const float* x  = (const float*)d_in[0];
    const float* Wq = (const float*)d_in[1];
    const float* bq = (const float*)d_in[2];
    const float* Wk = (const float*)d_in[3];
    const float* bk = (const float*)d_in[4];
    const float* Wv = (const float*)d_in[5];
    const float* bv = (const float*)d_in[6];
    const float* Wo = (const float*)d_in[7];
    const float* bo = (const float*)d_in[8];
    const float* P  = (const float*)d_in[9];
    float* out = (float*)d_out;

    cudaFuncSetAttribute(o_feat_kernel,
                         cudaFuncAttributeMaxDynamicSharedMemorySize, 68736);
    cudaFuncSetAttribute(gemm_mma,
                         cudaFuncAttributeMaxDynamicSharedMemorySize, NSTAGE * STAGE_B);

    // Split conversions
    conv_split<<<16384, 256>>>(x,  0, 4194304);
    conv_split<<<1024,  256>>>(Wq, 1, 262144);
    conv_split<<<1024,  256>>>(Wk, 2, 262144);
    conv_split<<<1024,  256>>>(Wv, 3, 262144);
    conv_split<<<1024,  256>>>(Wo, 4, 262144);

    dim3 gg(8, 128);   // (N/128, M/128)
    gemm_mma<<<gg, 256, NSTAGE * STAGE_B>>>(0, 0, bq, nullptr, 0);   // q
    gemm_mma<<<gg, 256, NSTAGE * STAGE_B>>>(0, 1, bk, nullptr, 1);   // k
    gemm_mma<<<gg, 256, NSTAGE * STAGE_B>>>(0, 2, bv, nullptr, 2);   // v

    feat_kv_kernel<<<1024, 256>>>(P);
    kv_reduce_kernel<<<64, 256>>>();
    o_feat_kernel<<<2048, 256, 68736>>>(P);       // -> g_aohi/g_aolo

    gemm_mma<<<gg, 256, NSTAGE * STAGE_B>>>(1, 3, bo, out, -1);      // out proj
}